// round 1
// baseline (speedup 1.0000x reference)
#include <cuda_runtime.h>
#include <math_constants.h>

#define DMODEL 1024
#define SEQ    2048
#define BATCH  2
#define MROWS  (BATCH * SEQ)
#define NHEADS 16
#define DK     64

// Scratch (allocation-free rule: __device__ globals)
__device__ float g_qp[MROWS * DMODEL];
__device__ float g_kp[MROWS * DMODEL];
__device__ float g_vp[MROWS * DMODEL];
__device__ float g_ao[MROWS * DMODEL];

// ---------------------------------------------------------------------------
// C[M,1024] = A[M,1024] @ W[1024,1024]^T + bias   (torch Linear, NT layout)
// 64x64 tile, BK=16, 256 threads, 4x4 microtile per thread.
// ---------------------------------------------------------------------------
__global__ __launch_bounds__(256) void sgemm_nt_bias(
    const float* __restrict__ A, const float* __restrict__ W,
    const float* __restrict__ bias, float* __restrict__ C)
{
    __shared__ float As[16][64];
    __shared__ float Ws[16][64];
    const int bm = blockIdx.y * 64;
    const int bn = blockIdx.x * 64;
    const int tid = threadIdx.x;
    const int tx = tid & 15;
    const int ty = tid >> 4;
    const int lr = tid >> 2;           // 0..63 : row within tile
    const int lc = (tid & 3) << 2;     // 0,4,8,12 : k-offset within BK

    const float* Ap = A + (size_t)(bm + lr) * DMODEL + lc;
    const float* Wp = W + (size_t)(bn + lr) * DMODEL + lc;

    float acc[4][4] = {};

    for (int k0 = 0; k0 < DMODEL; k0 += 16) {
        float4 a = *(const float4*)(Ap + k0);
        float4 w = *(const float4*)(Wp + k0);
        As[lc + 0][lr] = a.x; As[lc + 1][lr] = a.y;
        As[lc + 2][lr] = a.z; As[lc + 3][lr] = a.w;
        Ws[lc + 0][lr] = w.x; Ws[lc + 1][lr] = w.y;
        Ws[lc + 2][lr] = w.z; Ws[lc + 3][lr] = w.w;
        __syncthreads();
#pragma unroll
        for (int k = 0; k < 16; k++) {
            float4 av = *(const float4*)&As[k][ty << 2];
            float4 wv = *(const float4*)&Ws[k][tx << 2];
            float ar[4] = {av.x, av.y, av.z, av.w};
            float br[4] = {wv.x, wv.y, wv.z, wv.w};
#pragma unroll
            for (int i = 0; i < 4; i++)
#pragma unroll
                for (int j = 0; j < 4; j++)
                    acc[i][j] += ar[i] * br[j];
        }
        __syncthreads();
    }

    const int col = bn + (tx << 2);
    float4 bb = *(const float4*)(bias + col);
#pragma unroll
    for (int i = 0; i < 4; i++) {
        int row = bm + (ty << 2) + i;
        float4 o = make_float4(acc[i][0] + bb.x, acc[i][1] + bb.y,
                               acc[i][2] + bb.z, acc[i][3] + bb.w);
        *(float4*)(C + (size_t)row * DMODEL + col) = o;
    }
}

// ---------------------------------------------------------------------------
// Flash-style attention over g_qp/g_kp/g_vp -> g_ao.
// grid: (SEQ/64, NHEADS, BATCH), block: 128 threads.
// Thread pair (2q, 2q+1) owns query q: each lane handles 32 of the 64 dims
// and 32 of the 64 keys per tile (exp computed exactly once per score).
// Smem: K tile + V tile + P (probs, transposed [key][query]) = 48 KB exactly.
// ---------------------------------------------------------------------------
__global__ __launch_bounds__(128) void attn_kernel()
{
    __shared__ float Ks[64][64];
    __shared__ float Vs[64][64];
    __shared__ float Ps[64][64];   // [key][query] -> conflict-free broadcast reads

    const int tid  = threadIdx.x;
    const int q    = tid >> 1;     // query within block (0..63)
    const int half = tid & 1;      // which 32-dim / 32-key half this lane owns
    const int h    = blockIdx.y;
    const int b    = blockIdx.z;
    const int qrow = b * SEQ + blockIdx.x * 64 + q;
    const float scale = 0.125f;    // 1/sqrt(DK)

    float qreg[32];
    const float* qp = g_qp + (size_t)qrow * DMODEL + h * DK + half * 32;
#pragma unroll
    for (int j4 = 0; j4 < 8; j4++) {
        float4 v = *(const float4*)(qp + j4 * 4);
        qreg[j4 * 4 + 0] = v.x * scale;
        qreg[j4 * 4 + 1] = v.y * scale;
        qreg[j4 * 4 + 2] = v.z * scale;
        qreg[j4 * 4 + 3] = v.w * scale;
    }

    float m = -CUDART_INF_F;
    float l = 0.f;
    float acc[32];
#pragma unroll
    for (int d = 0; d < 32; d++) acc[d] = 0.f;

    const float* kb = g_kp + (size_t)b * SEQ * DMODEL + h * DK;
    const float* vb = g_vp + (size_t)b * SEQ * DMODEL + h * DK;

    for (int kt = 0; kt < SEQ; kt += 64) {
        // Load K/V tiles: 1024 float4 each, fully coalesced (16 thr per row).
#pragma unroll
        for (int i = 0; i < 8; i++) {
            int idx4 = tid + i * 128;
            int row  = idx4 >> 4;
            int col  = (idx4 & 15) << 2;
            *(float4*)&Ks[row][col] =
                *(const float4*)(kb + (size_t)(kt + row) * DMODEL + col);
            *(float4*)&Vs[row][col] =
                *(const float4*)(vb + (size_t)(kt + row) * DMODEL + col);
        }
        __syncthreads();

        // Phase 1: scores. Each lane dots its 32 dims; pair-shuffle completes.
#pragma unroll 4
        for (int kk = 0; kk < 64; kk++) {
            float part = 0.f;
#pragma unroll
            for (int j4 = 0; j4 < 8; j4++) {
                float4 kv = *(const float4*)&Ks[kk][half * 32 + j4 * 4];
                part += qreg[j4 * 4 + 0] * kv.x + qreg[j4 * 4 + 1] * kv.y
                      + qreg[j4 * 4 + 2] * kv.z + qreg[j4 * 4 + 3] * kv.w;
            }
            float s = part + __shfl_xor_sync(0xffffffffu, part, 1);
            if ((kk >> 5) == half) Ps[kk][q] = s;   // each lane owns 32 keys
        }

        // Phase 2: online softmax over own-half keys (exp computed once).
        float tm = -CUDART_INF_F;
#pragma unroll 4
        for (int i = 0; i < 32; i++) tm = fmaxf(tm, Ps[half * 32 + i][q]);
        tm = fmaxf(tm, __shfl_xor_sync(0xffffffffu, tm, 1));
        float mnew = fmaxf(m, tm);
        float c = __expf(m - mnew);   // exp(-inf)=0 on first tile
        m = mnew;
        l *= c;
#pragma unroll
        for (int d = 0; d < 32; d++) acc[d] *= c;
#pragma unroll 4
        for (int i = 0; i < 32; i++) {
            float p = __expf(Ps[half * 32 + i][q] - mnew);
            l += p;
            Ps[half * 32 + i][q] = p;
        }
        __syncwarp();   // pair lanes exchange P through smem (same warp)

        // Phase 3: accumulate O += P @ V (this lane's 32 dims, all 64 keys).
#pragma unroll 2
        for (int kk = 0; kk < 64; kk++) {
            float p = Ps[kk][q];
#pragma unroll
            for (int j4 = 0; j4 < 8; j4++) {
                float4 v = *(const float4*)&Vs[kk][half * 32 + j4 * 4];
                acc[j4 * 4 + 0] += p * v.x;
                acc[j4 * 4 + 1] += p * v.y;
                acc[j4 * 4 + 2] += p * v.z;
                acc[j4 * 4 + 3] += p * v.w;
            }
        }
        __syncthreads();   // protect Ks/Vs/Ps before next tile
    }

    float lsum = l + __shfl_xor_sync(0xffffffffu, l, 1);
    float inv = 1.0f / lsum;
    float* op = g_ao + (size_t)qrow * DMODEL + h * DK + half * 32;
#pragma unroll
    for (int j4 = 0; j4 < 8; j4++) {
        float4 o = make_float4(acc[j4 * 4 + 0] * inv, acc[j4 * 4 + 1] * inv,
                               acc[j4 * 4 + 2] * inv, acc[j4 * 4 + 3] * inv);
        *(float4*)(op + j4 * 4) = o;
    }
}

// ---------------------------------------------------------------------------
extern "C" void kernel_launch(void* const* d_in, const int* in_sizes, int n_in,
                              void* d_out, int out_size)
{
    const float* v  = (const float*)d_in[0];
    const float* k  = (const float*)d_in[1];
    const float* q  = (const float*)d_in[2];
    const float* Wv = (const float*)d_in[3];
    const float* bv = (const float*)d_in[4];
    const float* Wk = (const float*)d_in[5];
    const float* bk = (const float*)d_in[6];
    const float* Wq = (const float*)d_in[7];
    const float* bq = (const float*)d_in[8];
    const float* Wo = (const float*)d_in[9];
    const float* bo = (const float*)d_in[10];
    float* out = (float*)d_out;

    float *qp, *kp, *vp, *ao;
    cudaGetSymbolAddress((void**)&qp, g_qp);
    cudaGetSymbolAddress((void**)&kp, g_kp);
    cudaGetSymbolAddress((void**)&vp, g_vp);
    cudaGetSymbolAddress((void**)&ao, g_ao);

    dim3 gemm_grid(DMODEL / 64, MROWS / 64);   // (16, 64)
    sgemm_nt_bias<<<gemm_grid, 256>>>(q, Wq, bq, qp);
    sgemm_nt_bias<<<gemm_grid, 256>>>(k, Wk, bk, kp);
    sgemm_nt_bias<<<gemm_grid, 256>>>(v, Wv, bv, vp);

    dim3 attn_grid(SEQ / 64, NHEADS, BATCH);   // (32, 16, 2)
    attn_kernel<<<attn_grid, 128>>>();

    sgemm_nt_bias<<<gemm_grid, 256>>>(ao, Wo, bo, out);
}

// round 3
// speedup vs baseline: 1.3491x; 1.3491x over previous
#include <cuda_runtime.h>
#include <math_constants.h>
#include <cstdint>

#define DMODEL 1024
#define SEQ    2048
#define BATCH  2
#define MROWS  (BATCH * SEQ)
#define NHEADS 16
#define DK     64

// Scratch (allocation-free rule: __device__ globals)
__device__ float g_qp[MROWS * DMODEL];
__device__ float g_kp[MROWS * DMODEL];
__device__ float g_vp[MROWS * DMODEL];
__device__ float g_ao[MROWS * DMODEL];

// ===========================================================================
// PTX helpers (baseline compute_103-safe: mma.sync + cp.async only)
// ===========================================================================
__device__ __forceinline__ uint32_t smem_u32(const void* p) {
    uint32_t a;
    asm("{ .reg .u64 t; cvta.to.shared.u64 t, %1; cvt.u32.u64 %0, t; }"
        : "=r"(a) : "l"(p));
    return a;
}
#define CP_ASYNC16(smem, gptr)                                                 \
    asm volatile("cp.async.cg.shared.global [%0], [%1], 16;"                   \
                 :: "r"(smem), "l"(gptr))
#define CP_COMMIT() asm volatile("cp.async.commit_group;" ::: "memory")
#define CP_WAIT0()  asm volatile("cp.async.wait_group 0;" ::: "memory")

__device__ __forceinline__ uint32_t f2tf32(float x) {
    uint32_t u;
    asm("cvt.rna.tf32.f32 %0, %1;" : "=r"(u) : "f"(x));
    return u;
}
__device__ __forceinline__ void mma_tf32(float& c0, float& c1, float& c2, float& c3,
                                         uint32_t a0, uint32_t a1, uint32_t a2, uint32_t a3,
                                         uint32_t b0, uint32_t b1) {
    asm volatile(
        "mma.sync.aligned.m16n8k8.row.col.f32.tf32.tf32.f32 "
        "{%0,%1,%2,%3}, {%4,%5,%6,%7}, {%8,%9}, {%0,%1,%2,%3};"
        : "+f"(c0), "+f"(c1), "+f"(c2), "+f"(c3)
        : "r"(a0), "r"(a1), "r"(a2), "r"(a3), "r"(b0), "r"(b1));
}

// ===========================================================================
// tf32 mma.sync GEMM:  C[M,1024] = A[M,1024] @ W[1024,1024]^T + bias
// 128x128 CTA tile, BK=32, 256 threads (8 warps, 2x4), warp tile 64x32.
// Double-buffered cp.async smem, padded ld=36 floats (conflict-free frags).
// blockIdx.z selects job (fused QKV).
// ===========================================================================
struct GemmJob { const float* A; const float* W; const float* bias; float* C; };
struct GemmParams { GemmJob job[3]; };

#define GBM 128
#define GBN 128
#define GBK 32
#define GNIT (DMODEL / GBK)            // 32
#define LDT 36                         // padded floats per tile row
#define TILEF (128 * LDT)              // floats per (A or B) buffer: 4608
#define SMEM_REQ (4 * TILEF * 4)       // 2 bufs x (A+B) = 73728 B

__global__ __launch_bounds__(256) void gemm_tf32(GemmParams p)
{
    extern __shared__ float dsm[];
    // layout: A0 [0,TILEF) A1 [TILEF,2T) B0 [2T,3T) B1 [3T,4T)
    float* As = dsm;
    float* Bs = dsm + 2 * TILEF;
    const uint32_t sa = smem_u32(dsm);

    const GemmJob j = p.job[blockIdx.z];
    const int bm = blockIdx.y * GBM;
    const int bn = blockIdx.x * GBN;
    const int tid = threadIdx.x;
    const int wid = tid >> 5;
    const int lid = tid & 31;
    const int wm = (wid >> 2) * 64;    // warp M offset within tile (0,64)
    const int wn = (wid & 3) * 32;     // warp N offset within tile (0..96)
    const int g = lid >> 2;            // fragment group row 0..7
    const int t = lid & 3;             // fragment k 0..3

    // global load geometry: each thread covers 4 rows (row0 + 32*jj), one float4
    const int row0 = tid >> 3;
    const int c4 = (tid & 7) * 4;
    const float* Ag[4];
    const float* Wg[4];
    uint32_t sAoff[4], sBoff[4];
#pragma unroll
    for (int jj = 0; jj < 4; jj++) {
        int row = row0 + jj * 32;
        Ag[jj] = j.A + (size_t)(bm + row) * DMODEL + c4;
        Wg[jj] = j.W + (size_t)(bn + row) * DMODEL + c4;
        sAoff[jj] = (uint32_t)((row * LDT + c4) * 4);
        sBoff[jj] = (uint32_t)((2 * TILEF + row * LDT + c4) * 4);
    }

    // prologue: buffer 0
#pragma unroll
    for (int jj = 0; jj < 4; jj++) {
        CP_ASYNC16(sa + sAoff[jj], Ag[jj]);
        CP_ASYNC16(sa + sBoff[jj], Wg[jj]);
    }
    CP_COMMIT();

    float acc[4][4][4];
#pragma unroll
    for (int mt = 0; mt < 4; mt++)
#pragma unroll
        for (int nt = 0; nt < 4; nt++)
#pragma unroll
            for (int r = 0; r < 4; r++) acc[mt][nt][r] = 0.f;

    for (int it = 0; it < GNIT; it++) {
        CP_WAIT0();
        __syncthreads();

        if (it + 1 < GNIT) {
            const uint32_t dst = (uint32_t)(((it + 1) & 1) * TILEF * 4);
            const int koff = (it + 1) * GBK;
#pragma unroll
            for (int jj = 0; jj < 4; jj++) {
                CP_ASYNC16(sa + sAoff[jj] + dst, Ag[jj] + koff);
                CP_ASYNC16(sa + sBoff[jj] + dst, Wg[jj] + koff);
            }
            CP_COMMIT();
        }

        const float* Ab = As + (it & 1) * TILEF;
        const float* Bb = Bs + (it & 1) * TILEF;

#pragma unroll
        for (int ks = 0; ks < 4; ks++) {
            const int kb = ks * 8;
            // B fragments: b0 = B[k=t, n=g], b1 = B[k=t+4, n=g]; Bs[n][k]
            uint32_t bf[4][2];
#pragma unroll
            for (int nt = 0; nt < 4; nt++) {
                const float* bp = Bb + (wn + nt * 8 + g) * LDT + kb + t;
                bf[nt][0] = f2tf32(bp[0]);
                bf[nt][1] = f2tf32(bp[4]);
            }
#pragma unroll
            for (int mt = 0; mt < 4; mt++) {
                const float* ap = Ab + (wm + mt * 16 + g) * LDT + kb + t;
                uint32_t a0 = f2tf32(ap[0]);
                uint32_t a1 = f2tf32(ap[8 * LDT]);
                uint32_t a2 = f2tf32(ap[4]);
                uint32_t a3 = f2tf32(ap[8 * LDT + 4]);
#pragma unroll
                for (int nt = 0; nt < 4; nt++)
                    mma_tf32(acc[mt][nt][0], acc[mt][nt][1],
                             acc[mt][nt][2], acc[mt][nt][3],
                             a0, a1, a2, a3, bf[nt][0], bf[nt][1]);
            }
        }
        __syncthreads();
    }

    // epilogue: c0=[g,2t] c1=[g,2t+1] c2=[g+8,2t] c3=[g+8,2t+1] per 16x8 tile
#pragma unroll
    for (int mt = 0; mt < 4; mt++) {
        const int row = bm + wm + mt * 16 + g;
#pragma unroll
        for (int nt = 0; nt < 4; nt++) {
            const int col = bn + wn + nt * 8 + 2 * t;
            const float b0 = j.bias[col], b1 = j.bias[col + 1];
            float* c0p = j.C + (size_t)row * DMODEL + col;
            float* c1p = j.C + (size_t)(row + 8) * DMODEL + col;
            *(float2*)c0p = make_float2(acc[mt][nt][0] + b0, acc[mt][nt][1] + b1);
            *(float2*)c1p = make_float2(acc[mt][nt][2] + b0, acc[mt][nt][3] + b1);
        }
    }
}

// ===========================================================================
// Flash-style attention (unchanged from R1): grid (SEQ/64, H, B), 128 thr.
// ===========================================================================
__global__ __launch_bounds__(128) void attn_kernel()
{
    __shared__ float Ks[64][64];
    __shared__ float Vs[64][64];
    __shared__ float Ps[64][64];

    const int tid  = threadIdx.x;
    const int q    = tid >> 1;
    const int half = tid & 1;
    const int h    = blockIdx.y;
    const int b    = blockIdx.z;
    const int qrow = b * SEQ + blockIdx.x * 64 + q;
    const float scale = 0.125f;

    float qreg[32];
    const float* qp = g_qp + (size_t)qrow * DMODEL + h * DK + half * 32;
#pragma unroll
    for (int j4 = 0; j4 < 8; j4++) {
        float4 v = *(const float4*)(qp + j4 * 4);
        qreg[j4 * 4 + 0] = v.x * scale;
        qreg[j4 * 4 + 1] = v.y * scale;
        qreg[j4 * 4 + 2] = v.z * scale;
        qreg[j4 * 4 + 3] = v.w * scale;
    }

    float m = -CUDART_INF_F;
    float l = 0.f;
    float acc[32];
#pragma unroll
    for (int d = 0; d < 32; d++) acc[d] = 0.f;

    const float* kb = g_kp + (size_t)b * SEQ * DMODEL + h * DK;
    const float* vb = g_vp + (size_t)b * SEQ * DMODEL + h * DK;

    for (int kt = 0; kt < SEQ; kt += 64) {
#pragma unroll
        for (int i = 0; i < 8; i++) {
            int idx4 = tid + i * 128;
            int row  = idx4 >> 4;
            int col  = (idx4 & 15) << 2;
            *(float4*)&Ks[row][col] =
                *(const float4*)(kb + (size_t)(kt + row) * DMODEL + col);
            *(float4*)&Vs[row][col] =
                *(const float4*)(vb + (size_t)(kt + row) * DMODEL + col);
        }
        __syncthreads();

#pragma unroll 4
        for (int kk = 0; kk < 64; kk++) {
            float part = 0.f;
#pragma unroll
            for (int j4 = 0; j4 < 8; j4++) {
                float4 kv = *(const float4*)&Ks[kk][half * 32 + j4 * 4];
                part += qreg[j4 * 4 + 0] * kv.x + qreg[j4 * 4 + 1] * kv.y
                      + qreg[j4 * 4 + 2] * kv.z + qreg[j4 * 4 + 3] * kv.w;
            }
            float s = part + __shfl_xor_sync(0xffffffffu, part, 1);
            if ((kk >> 5) == half) Ps[kk][q] = s;
        }

        float tm = -CUDART_INF_F;
#pragma unroll 4
        for (int i = 0; i < 32; i++) tm = fmaxf(tm, Ps[half * 32 + i][q]);
        tm = fmaxf(tm, __shfl_xor_sync(0xffffffffu, tm, 1));
        float mnew = fmaxf(m, tm);
        float c = __expf(m - mnew);
        m = mnew;
        l *= c;
#pragma unroll
        for (int d = 0; d < 32; d++) acc[d] *= c;
#pragma unroll 4
        for (int i = 0; i < 32; i++) {
            float p = __expf(Ps[half * 32 + i][q] - mnew);
            l += p;
            Ps[half * 32 + i][q] = p;
        }
        __syncwarp();

#pragma unroll 2
        for (int kk = 0; kk < 64; kk++) {
            float p = Ps[kk][q];
#pragma unroll
            for (int j4 = 0; j4 < 8; j4++) {
                float4 v = *(const float4*)&Vs[kk][half * 32 + j4 * 4];
                acc[j4 * 4 + 0] += p * v.x;
                acc[j4 * 4 + 1] += p * v.y;
                acc[j4 * 4 + 2] += p * v.z;
                acc[j4 * 4 + 3] += p * v.w;
            }
        }
        __syncthreads();
    }

    float lsum = l + __shfl_xor_sync(0xffffffffu, l, 1);
    float inv = 1.0f / lsum;
    float* op = g_ao + (size_t)qrow * DMODEL + h * DK + half * 32;
#pragma unroll
    for (int j4 = 0; j4 < 8; j4++) {
        float4 o = make_float4(acc[j4 * 4 + 0] * inv, acc[j4 * 4 + 1] * inv,
                               acc[j4 * 4 + 2] * inv, acc[j4 * 4 + 3] * inv);
        *(float4*)(op + j4 * 4) = o;
    }
}

// ===========================================================================
extern "C" void kernel_launch(void* const* d_in, const int* in_sizes, int n_in,
                              void* d_out, int out_size)
{
    const float* v  = (const float*)d_in[0];
    const float* k  = (const float*)d_in[1];
    const float* q  = (const float*)d_in[2];
    const float* Wv = (const float*)d_in[3];
    const float* bv = (const float*)d_in[4];
    const float* Wk = (const float*)d_in[5];
    const float* bk = (const float*)d_in[6];
    const float* Wq = (const float*)d_in[7];
    const float* bq = (const float*)d_in[8];
    const float* Wo = (const float*)d_in[9];
    const float* bo = (const float*)d_in[10];
    float* out = (float*)d_out;

    float *qp, *kp, *vp, *ao;
    cudaGetSymbolAddress((void**)&qp, g_qp);
    cudaGetSymbolAddress((void**)&kp, g_kp);
    cudaGetSymbolAddress((void**)&vp, g_vp);
    cudaGetSymbolAddress((void**)&ao, g_ao);

    static bool attr_set = false;
    if (!attr_set) {
        cudaFuncSetAttribute(gemm_tf32,
                             cudaFuncAttributeMaxDynamicSharedMemorySize, SMEM_REQ);
        attr_set = true;
    }

    GemmParams pin;
    pin.job[0] = { q, Wq, bq, qp };
    pin.job[1] = { k, Wk, bk, kp };
    pin.job[2] = { v, Wv, bv, vp };
    dim3 ggrid(DMODEL / GBN, MROWS / GBM, 3);   // (8, 32, 3)
    gemm_tf32<<<ggrid, 256, SMEM_REQ>>>(pin);

    dim3 attn_grid(SEQ / 64, NHEADS, BATCH);    // (32, 16, 2)
    attn_kernel<<<attn_grid, 128>>>();

    GemmParams pout;
    pout.job[0] = { ao, Wo, bo, out };
    pout.job[1] = { ao, Wo, bo, out };
    pout.job[2] = { ao, Wo, bo, out };
    dim3 ogrid(DMODEL / GBN, MROWS / GBM, 1);   // (8, 32, 1)
    gemm_tf32<<<ogrid, 256, SMEM_REQ>>>(pout);
}

// round 4
// speedup vs baseline: 2.8380x; 2.1036x over previous
#include <cuda_runtime.h>
#include <math_constants.h>
#include <cstdint>

#define DMODEL 1024
#define SEQ    2048
#define BATCH  2
#define MROWS  (BATCH * SEQ)
#define NHEADS 16
#define DK     64

// Scratch (allocation-free rule: __device__ globals)
__device__ float g_qp[MROWS * DMODEL];
__device__ float g_kp[MROWS * DMODEL];
__device__ float g_vp[MROWS * DMODEL];
__device__ float g_ao[MROWS * DMODEL];

// ===========================================================================
// PTX helpers (baseline compute_103-safe: mma.sync + cp.async only)
// ===========================================================================
__device__ __forceinline__ uint32_t smem_u32(const void* p) {
    uint32_t a;
    asm("{ .reg .u64 t; cvta.to.shared.u64 t, %1; cvt.u32.u64 %0, t; }"
        : "=r"(a) : "l"(p));
    return a;
}
#define CP_ASYNC16(smem, gptr)                                                 \
    asm volatile("cp.async.cg.shared.global [%0], [%1], 16;"                   \
                 :: "r"(smem), "l"(gptr))
#define CP_COMMIT() asm volatile("cp.async.commit_group;" ::: "memory")
#define CP_WAIT0()  asm volatile("cp.async.wait_group 0;" ::: "memory")

__device__ __forceinline__ uint32_t f2tf32(float x) {
    uint32_t u;
    asm("cvt.rna.tf32.f32 %0, %1;" : "=r"(u) : "f"(x));
    return u;
}
__device__ __forceinline__ void mma_tf32(float& c0, float& c1, float& c2, float& c3,
                                         uint32_t a0, uint32_t a1, uint32_t a2, uint32_t a3,
                                         uint32_t b0, uint32_t b1) {
    asm volatile(
        "mma.sync.aligned.m16n8k8.row.col.f32.tf32.tf32.f32 "
        "{%0,%1,%2,%3}, {%4,%5,%6,%7}, {%8,%9}, {%0,%1,%2,%3};"
        : "+f"(c0), "+f"(c1), "+f"(c2), "+f"(c3)
        : "r"(a0), "r"(a1), "r"(a2), "r"(a3), "r"(b0), "r"(b1));
}

// exp2 via FMA polynomial (avoids MUFU pipe; ~1e-7 rel). Input must be <= 0.
__device__ __forceinline__ float exp2poly(float z) {
    z = fmaxf(z, -126.0f);
    float fl = floorf(z);
    float f = z - fl;
    float p =              1.535336188319500e-4f;
    p = fmaf(p, f, 1.339887440266574e-3f);
    p = fmaf(p, f, 9.618437357674640e-3f);
    p = fmaf(p, f, 5.550332471162809e-2f);
    p = fmaf(p, f, 2.402264791363012e-1f);
    p = fmaf(p, f, 6.931472028550421e-1f);
    p = fmaf(p, f, 1.0f);
    return __int_as_float(__float_as_int(p) + (((int)fl) << 23));
}
#define LOG2E 1.4426950408889634f

// ===========================================================================
// tf32 mma.sync GEMM:  C[M,1024] = A[M,1024] @ W[1024,1024]^T + bias
// (unchanged from R3: 128x128 CTA tile, BK=32, 8 warps, double-buffered)
// ===========================================================================
struct GemmJob { const float* A; const float* W; const float* bias; float* C; };
struct GemmParams { GemmJob job[3]; };

#define GBM 128
#define GBN 128
#define GBK 32
#define GNIT (DMODEL / GBK)
#define LDT 36
#define TILEF (128 * LDT)
#define SMEM_REQ (4 * TILEF * 4)

__global__ __launch_bounds__(256) void gemm_tf32(GemmParams p)
{
    extern __shared__ float dsm[];
    float* As = dsm;
    float* Bs = dsm + 2 * TILEF;
    const uint32_t sa = smem_u32(dsm);

    const GemmJob j = p.job[blockIdx.z];
    const int bm = blockIdx.y * GBM;
    const int bn = blockIdx.x * GBN;
    const int tid = threadIdx.x;
    const int wid = tid >> 5;
    const int lid = tid & 31;
    const int wm = (wid >> 2) * 64;
    const int wn = (wid & 3) * 32;
    const int g = lid >> 2;
    const int t = lid & 3;

    const int row0 = tid >> 3;
    const int c4 = (tid & 7) * 4;
    const float* Ag[4];
    const float* Wg[4];
    uint32_t sAoff[4], sBoff[4];
#pragma unroll
    for (int jj = 0; jj < 4; jj++) {
        int row = row0 + jj * 32;
        Ag[jj] = j.A + (size_t)(bm + row) * DMODEL + c4;
        Wg[jj] = j.W + (size_t)(bn + row) * DMODEL + c4;
        sAoff[jj] = (uint32_t)((row * LDT + c4) * 4);
        sBoff[jj] = (uint32_t)((2 * TILEF + row * LDT + c4) * 4);
    }

#pragma unroll
    for (int jj = 0; jj < 4; jj++) {
        CP_ASYNC16(sa + sAoff[jj], Ag[jj]);
        CP_ASYNC16(sa + sBoff[jj], Wg[jj]);
    }
    CP_COMMIT();

    float acc[4][4][4];
#pragma unroll
    for (int mt = 0; mt < 4; mt++)
#pragma unroll
        for (int nt = 0; nt < 4; nt++)
#pragma unroll
            for (int r = 0; r < 4; r++) acc[mt][nt][r] = 0.f;

    for (int it = 0; it < GNIT; it++) {
        CP_WAIT0();
        __syncthreads();

        if (it + 1 < GNIT) {
            const uint32_t dst = (uint32_t)(((it + 1) & 1) * TILEF * 4);
            const int koff = (it + 1) * GBK;
#pragma unroll
            for (int jj = 0; jj < 4; jj++) {
                CP_ASYNC16(sa + sAoff[jj] + dst, Ag[jj] + koff);
                CP_ASYNC16(sa + sBoff[jj] + dst, Wg[jj] + koff);
            }
            CP_COMMIT();
        }

        const float* Ab = As + (it & 1) * TILEF;
        const float* Bb = Bs + (it & 1) * TILEF;

#pragma unroll
        for (int ks = 0; ks < 4; ks++) {
            const int kb = ks * 8;
            uint32_t bf[4][2];
#pragma unroll
            for (int nt = 0; nt < 4; nt++) {
                const float* bp = Bb + (wn + nt * 8 + g) * LDT + kb + t;
                bf[nt][0] = f2tf32(bp[0]);
                bf[nt][1] = f2tf32(bp[4]);
            }
#pragma unroll
            for (int mt = 0; mt < 4; mt++) {
                const float* ap = Ab + (wm + mt * 16 + g) * LDT + kb + t;
                uint32_t a0 = f2tf32(ap[0]);
                uint32_t a1 = f2tf32(ap[8 * LDT]);
                uint32_t a2 = f2tf32(ap[4]);
                uint32_t a3 = f2tf32(ap[8 * LDT + 4]);
#pragma unroll
                for (int nt = 0; nt < 4; nt++)
                    mma_tf32(acc[mt][nt][0], acc[mt][nt][1],
                             acc[mt][nt][2], acc[mt][nt][3],
                             a0, a1, a2, a3, bf[nt][0], bf[nt][1]);
            }
        }
        __syncthreads();
    }

#pragma unroll
    for (int mt = 0; mt < 4; mt++) {
        const int row = bm + wm + mt * 16 + g;
#pragma unroll
        for (int nt = 0; nt < 4; nt++) {
            const int col = bn + wn + nt * 8 + 2 * t;
            const float b0 = j.bias[col], b1 = j.bias[col + 1];
            float* c0p = j.C + (size_t)row * DMODEL + col;
            float* c1p = j.C + (size_t)(row + 8) * DMODEL + col;
            *(float2*)c0p = make_float2(acc[mt][nt][0] + b0, acc[mt][nt][1] + b1);
            *(float2*)c1p = make_float2(acc[mt][nt][2] + b0, acc[mt][nt][3] + b1);
        }
    }
}

// ===========================================================================
// Tensor-core flash attention (tf32 mma.sync, 3-term error compensation).
// grid (SEQ/64, H, B), 128 threads = 4 warps; warp w owns query rows w*16..+16.
// QK:  S = qb*kb + qs*kb + qb*ks    (residual ~eps^2)
// PV:  O += pb*vb + ps*vb + pb*vs   (residual ~eps^2)
// Softmax SIMT over smem S tile with FMA-poly exp2.
// ===========================================================================
#define ALD 68   // ld for Ks/Pb/Ps  (ld % 32 == 4 -> frag LDS conflict-free)
#define VLD 72   // ld for Vs        (ld % 32 == 8 -> frag LDS conflict-free)
// smem floats: Ks 64*68=4352 | Vs 64*72=4608 | Pb 4352 | Ps 4352 | stats 192
#define ATT_SMEMF (4352 + 4608 + 4352 + 4352 + 192)
#define ATT_SMEMB (ATT_SMEMF * 4)

__global__ __launch_bounds__(128) void attn_mma()
{
    extern __shared__ float sm[];
    float* Ks   = sm;
    float* Vs   = sm + 4352;
    float* Pb   = sm + 8960;
    float* Ps   = sm + 13312;
    float* mrow = sm + 17664;
    float* lrow = sm + 17728;
    float* crow = sm + 17792;

    const int tid = threadIdx.x;
    const int wid = tid >> 5;
    const int lid = tid & 31;
    const int g = lid >> 2;
    const int t = lid & 3;
    const int m0 = wid * 16;
    const int h = blockIdx.y;
    const int b = blockIdx.z;
    const int qbase = b * SEQ + blockIdx.x * 64;

    const float* qg = g_qp + (size_t)qbase * DMODEL + h * DK;
    const float* kg = g_kp + (size_t)b * SEQ * DMODEL + h * DK;
    const float* vg = g_vp + (size_t)b * SEQ * DMODEL + h * DK;

    // ---- stage Q tile into Ks, init row stats ----
#pragma unroll
    for (int i = 0; i < 8; i++) {
        int idx = tid + i * 128;
        int r = idx >> 4, c = (idx & 15) << 2;
        *(float4*)&Ks[r * ALD + c] = *(const float4*)(qg + (size_t)r * DMODEL + c);
    }
    if (tid < 64) { mrow[tid] = -1e30f; lrow[tid] = 0.f; }
    __syncthreads();

    // ---- preload scaled+split Q fragments (A-frags for all 8 k-steps) ----
    uint32_t qb[8][4], qs[8][4];
#pragma unroll
    for (int ks = 0; ks < 8; ks++) {
        int kb = ks * 8;
        float f0 = Ks[(m0 + g) * ALD + kb + t] * 0.125f;
        float f1 = Ks[(m0 + g + 8) * ALD + kb + t] * 0.125f;
        float f2 = Ks[(m0 + g) * ALD + kb + t + 4] * 0.125f;
        float f3 = Ks[(m0 + g + 8) * ALD + kb + t + 4] * 0.125f;
        qb[ks][0] = f2tf32(f0); qs[ks][0] = f2tf32(f0 - __uint_as_float(qb[ks][0]));
        qb[ks][1] = f2tf32(f1); qs[ks][1] = f2tf32(f1 - __uint_as_float(qb[ks][1]));
        qb[ks][2] = f2tf32(f2); qs[ks][2] = f2tf32(f2 - __uint_as_float(qb[ks][2]));
        qb[ks][3] = f2tf32(f3); qs[ks][3] = f2tf32(f3 - __uint_as_float(qb[ks][3]));
    }
    __syncthreads();   // Ks about to be reused for K tiles

    float Oa[8][4];
#pragma unroll
    for (int nt = 0; nt < 8; nt++)
#pragma unroll
        for (int r = 0; r < 4; r++) Oa[nt][r] = 0.f;

    for (int kt = 0; kt < SEQ; kt += 64) {
        // ---- load K/V tiles (coalesced float4) ----
#pragma unroll
        for (int i = 0; i < 8; i++) {
            int idx = tid + i * 128;
            int r = idx >> 4, c = (idx & 15) << 2;
            *(float4*)&Ks[r * ALD + c] =
                *(const float4*)(kg + (size_t)(kt + r) * DMODEL + c);
            *(float4*)&Vs[r * VLD + c] =
                *(const float4*)(vg + (size_t)(kt + r) * DMODEL + c);
        }
        __syncthreads();

        // ---- QK^T (3-pass compensated tf32) ----
        float Sa[8][4];
#pragma unroll
        for (int nt = 0; nt < 8; nt++)
#pragma unroll
            for (int r = 0; r < 4; r++) Sa[nt][r] = 0.f;

#pragma unroll
        for (int ks = 0; ks < 8; ks++) {
            int kb = ks * 8;
#pragma unroll
            for (int nt = 0; nt < 8; nt++) {
                float b0f = Ks[(nt * 8 + g) * ALD + kb + t];
                float b1f = Ks[(nt * 8 + g) * ALD + kb + t + 4];
                uint32_t bb0 = f2tf32(b0f), bb1 = f2tf32(b1f);
                uint32_t bs0 = f2tf32(b0f - __uint_as_float(bb0));
                uint32_t bs1 = f2tf32(b1f - __uint_as_float(bb1));
                mma_tf32(Sa[nt][0], Sa[nt][1], Sa[nt][2], Sa[nt][3],
                         qb[ks][0], qb[ks][1], qb[ks][2], qb[ks][3], bb0, bb1);
                mma_tf32(Sa[nt][0], Sa[nt][1], Sa[nt][2], Sa[nt][3],
                         qs[ks][0], qs[ks][1], qs[ks][2], qs[ks][3], bb0, bb1);
                mma_tf32(Sa[nt][0], Sa[nt][1], Sa[nt][2], Sa[nt][3],
                         qb[ks][0], qb[ks][1], qb[ks][2], qb[ks][3], bs0, bs1);
            }
        }
        // scatter S fragments into Pb (as raw scores)
#pragma unroll
        for (int nt = 0; nt < 8; nt++) {
            int cc = nt * 8 + 2 * t;
            *(float2*)&Pb[(m0 + g) * ALD + cc]     = make_float2(Sa[nt][0], Sa[nt][1]);
            *(float2*)&Pb[(m0 + g + 8) * ALD + cc] = make_float2(Sa[nt][2], Sa[nt][3]);
        }
        __syncthreads();

        // ---- online softmax (SIMT, 2 threads/row, poly exp2) ----
        {
            int row = tid >> 1, half = tid & 1;
            float* Sr = Pb + row * ALD + half * 32;
            float* Pr = Ps + row * ALD + half * 32;
            float sv[32];
            float mx = -1e30f;
#pragma unroll
            for (int i = 0; i < 32; i++) { sv[i] = Sr[i]; mx = fmaxf(mx, sv[i]); }
            mx = fmaxf(mx, __shfl_xor_sync(0xffffffffu, mx, 1));
            float mold = mrow[row];
            float mnew = fmaxf(mold, mx);
            float c = exp2poly((mold - mnew) * LOG2E);
            float ls = 0.f;
#pragma unroll
            for (int i = 0; i < 32; i++) {
                float p = exp2poly((sv[i] - mnew) * LOG2E);
                ls += p;
                uint32_t pbu = f2tf32(p);
                Sr[i] = __uint_as_float(pbu);                       // pb (tf32-exact)
                Pr[i] = __uint_as_float(f2tf32(p - __uint_as_float(pbu)));  // ps
            }
            ls += __shfl_xor_sync(0xffffffffu, ls, 1);
            if (half == 0) {
                mrow[row] = mnew;
                lrow[row] = lrow[row] * c + ls;
                crow[row] = c;
            }
        }
        __syncthreads();

        // ---- rescale O, then O += P*V (3-pass compensated) ----
        {
            float c0 = crow[m0 + g], c1 = crow[m0 + g + 8];
#pragma unroll
            for (int nt = 0; nt < 8; nt++) {
                Oa[nt][0] *= c0; Oa[nt][1] *= c0;
                Oa[nt][2] *= c1; Oa[nt][3] *= c1;
            }
        }
#pragma unroll
        for (int ks = 0; ks < 8; ks++) {
            int kb = ks * 8;
            uint32_t pb0 = __float_as_uint(Pb[(m0 + g) * ALD + kb + t]);
            uint32_t pb1 = __float_as_uint(Pb[(m0 + g + 8) * ALD + kb + t]);
            uint32_t pb2 = __float_as_uint(Pb[(m0 + g) * ALD + kb + t + 4]);
            uint32_t pb3 = __float_as_uint(Pb[(m0 + g + 8) * ALD + kb + t + 4]);
            uint32_t ps0 = __float_as_uint(Ps[(m0 + g) * ALD + kb + t]);
            uint32_t ps1 = __float_as_uint(Ps[(m0 + g + 8) * ALD + kb + t]);
            uint32_t ps2 = __float_as_uint(Ps[(m0 + g) * ALD + kb + t + 4]);
            uint32_t ps3 = __float_as_uint(Ps[(m0 + g + 8) * ALD + kb + t + 4]);
#pragma unroll
            for (int nt = 0; nt < 8; nt++) {
                float v0f = Vs[(kb + t) * VLD + nt * 8 + g];
                float v1f = Vs[(kb + t + 4) * VLD + nt * 8 + g];
                uint32_t vb0 = f2tf32(v0f), vb1 = f2tf32(v1f);
                uint32_t vs0 = f2tf32(v0f - __uint_as_float(vb0));
                uint32_t vs1 = f2tf32(v1f - __uint_as_float(vb1));
                mma_tf32(Oa[nt][0], Oa[nt][1], Oa[nt][2], Oa[nt][3],
                         pb0, pb1, pb2, pb3, vb0, vb1);
                mma_tf32(Oa[nt][0], Oa[nt][1], Oa[nt][2], Oa[nt][3],
                         ps0, ps1, ps2, ps3, vb0, vb1);
                mma_tf32(Oa[nt][0], Oa[nt][1], Oa[nt][2], Oa[nt][3],
                         pb0, pb1, pb2, pb3, vs0, vs1);
            }
        }
        __syncthreads();   // protect Ks/Vs/Pb/Ps before next tile
    }

    // ---- epilogue: normalize by l and store ----
    float inv0 = 1.0f / lrow[m0 + g];
    float inv1 = 1.0f / lrow[m0 + g + 8];
    float* o0 = g_ao + (size_t)(qbase + m0 + g) * DMODEL + h * DK;
    float* o1 = g_ao + (size_t)(qbase + m0 + g + 8) * DMODEL + h * DK;
#pragma unroll
    for (int nt = 0; nt < 8; nt++) {
        int cc = nt * 8 + 2 * t;
        *(float2*)(o0 + cc) = make_float2(Oa[nt][0] * inv0, Oa[nt][1] * inv0);
        *(float2*)(o1 + cc) = make_float2(Oa[nt][2] * inv1, Oa[nt][3] * inv1);
    }
}

// ===========================================================================
extern "C" void kernel_launch(void* const* d_in, const int* in_sizes, int n_in,
                              void* d_out, int out_size)
{
    const float* v  = (const float*)d_in[0];
    const float* k  = (const float*)d_in[1];
    const float* q  = (const float*)d_in[2];
    const float* Wv = (const float*)d_in[3];
    const float* bv = (const float*)d_in[4];
    const float* Wk = (const float*)d_in[5];
    const float* bk = (const float*)d_in[6];
    const float* Wq = (const float*)d_in[7];
    const float* bq = (const float*)d_in[8];
    const float* Wo = (const float*)d_in[9];
    const float* bo = (const float*)d_in[10];
    float* out = (float*)d_out;

    float *qp, *kp, *vp, *ao;
    cudaGetSymbolAddress((void**)&qp, g_qp);
    cudaGetSymbolAddress((void**)&kp, g_kp);
    cudaGetSymbolAddress((void**)&vp, g_vp);
    cudaGetSymbolAddress((void**)&ao, g_ao);

    static bool attr_set = false;
    if (!attr_set) {
        cudaFuncSetAttribute(gemm_tf32,
                             cudaFuncAttributeMaxDynamicSharedMemorySize, SMEM_REQ);
        cudaFuncSetAttribute(attn_mma,
                             cudaFuncAttributeMaxDynamicSharedMemorySize, ATT_SMEMB);
        attr_set = true;
    }

    GemmParams pin;
    pin.job[0] = { q, Wq, bq, qp };
    pin.job[1] = { k, Wk, bk, kp };
    pin.job[2] = { v, Wv, bv, vp };
    dim3 ggrid(DMODEL / GBN, MROWS / GBM, 3);   // (8, 32, 3)
    gemm_tf32<<<ggrid, 256, SMEM_REQ>>>(pin);

    dim3 attn_grid(SEQ / 64, NHEADS, BATCH);    // (32, 16, 2)
    attn_mma<<<attn_grid, 128, ATT_SMEMB>>>();

    GemmParams pout;
    pout.job[0] = { ao, Wo, bo, out };
    pout.job[1] = { ao, Wo, bo, out };
    pout.job[2] = { ao, Wo, bo, out };
    dim3 ogrid(DMODEL / GBN, MROWS / GBM, 1);   // (8, 32, 1)
    gemm_tf32<<<ogrid, 256, SMEM_REQ>>>(pout);
}

// round 5
// speedup vs baseline: 3.9346x; 1.3864x over previous
#include <cuda_runtime.h>
#include <math_constants.h>
#include <cstdint>

#define DMODEL 1024
#define SEQ    2048
#define BATCH  2
#define MROWS  (BATCH * SEQ)
#define NHEADS 16
#define DK     64

// Scratch (allocation-free rule: __device__ globals)
__device__ float g_qp[MROWS * DMODEL];
__device__ float g_kp[MROWS * DMODEL];
__device__ float g_vp[MROWS * DMODEL];
__device__ float g_ao[MROWS * DMODEL];

// ===========================================================================
// PTX helpers (baseline compute_103-safe: mma.sync + cp.async only)
// ===========================================================================
__device__ __forceinline__ uint32_t smem_u32(const void* p) {
    uint32_t a;
    asm("{ .reg .u64 t; cvta.to.shared.u64 t, %1; cvt.u32.u64 %0, t; }"
        : "=r"(a) : "l"(p));
    return a;
}
#define CP_ASYNC16(smem, gptr)                                                 \
    asm volatile("cp.async.cg.shared.global [%0], [%1], 16;"                   \
                 :: "r"(smem), "l"(gptr))
#define CP_COMMIT() asm volatile("cp.async.commit_group;" ::: "memory")
#define CP_WAIT(n)  asm volatile("cp.async.wait_group %0;" :: "n"(n) : "memory")

__device__ __forceinline__ uint32_t f2tf32(float x) {
    uint32_t u;
    asm("cvt.rna.tf32.f32 %0, %1;" : "=r"(u) : "f"(x));
    return u;
}
__device__ __forceinline__ void mma_tf32(float& c0, float& c1, float& c2, float& c3,
                                         uint32_t a0, uint32_t a1, uint32_t a2, uint32_t a3,
                                         uint32_t b0, uint32_t b1) {
    asm volatile(
        "mma.sync.aligned.m16n8k8.row.col.f32.tf32.tf32.f32 "
        "{%0,%1,%2,%3}, {%4,%5,%6,%7}, {%8,%9}, {%0,%1,%2,%3};"
        : "+f"(c0), "+f"(c1), "+f"(c2), "+f"(c3)
        : "r"(a0), "r"(a1), "r"(a2), "r"(a3), "r"(b0), "r"(b1));
}

// Fast exp2: magic-number round-to-nearest + Taylor-6 on [-0.5, 0.5].
// Pure FMA/ALU, no MUFU, no F2I. Input clamped to >= -126.
__device__ __forceinline__ float exp2m(float z) {
    z = fmaxf(z, -126.0f);
    float r = z + 12582912.0f;                 // 1.5 * 2^23 (RN rounding)
    int   n = __float_as_int(r) - 0x4B400000;  // integer part
    float f = z - (r - 12582912.0f);           // frac in [-0.5, 0.5]
    float p =              1.54035303933816e-4f;
    p = fmaf(p, f, 1.33335581464284e-3f);
    p = fmaf(p, f, 9.61812910762848e-3f);
    p = fmaf(p, f, 5.55041086648216e-2f);
    p = fmaf(p, f, 2.40226506959101e-1f);
    p = fmaf(p, f, 6.93147180559945e-1f);
    p = fmaf(p, f, 1.0f);
    return __int_as_float(__float_as_int(p) + (n << 23));
}
#define LOG2E 1.4426950408889634f

// ===========================================================================
// tf32 mma.sync GEMM (unchanged from R3/R4)
// ===========================================================================
struct GemmJob { const float* A; const float* W; const float* bias; float* C; };
struct GemmParams { GemmJob job[3]; };

#define GBM 128
#define GBN 128
#define GBK 32
#define GNIT (DMODEL / GBK)
#define LDT 36
#define TILEF (128 * LDT)
#define SMEM_REQ (4 * TILEF * 4)

__global__ __launch_bounds__(256) void gemm_tf32(GemmParams p)
{
    extern __shared__ float dsm[];
    float* As = dsm;
    float* Bs = dsm + 2 * TILEF;
    const uint32_t sa = smem_u32(dsm);

    const GemmJob j = p.job[blockIdx.z];
    const int bm = blockIdx.y * GBM;
    const int bn = blockIdx.x * GBN;
    const int tid = threadIdx.x;
    const int wid = tid >> 5;
    const int lid = tid & 31;
    const int wm = (wid >> 2) * 64;
    const int wn = (wid & 3) * 32;
    const int g = lid >> 2;
    const int t = lid & 3;

    const int row0 = tid >> 3;
    const int c4 = (tid & 7) * 4;
    const float* Ag[4];
    const float* Wg[4];
    uint32_t sAoff[4], sBoff[4];
#pragma unroll
    for (int jj = 0; jj < 4; jj++) {
        int row = row0 + jj * 32;
        Ag[jj] = j.A + (size_t)(bm + row) * DMODEL + c4;
        Wg[jj] = j.W + (size_t)(bn + row) * DMODEL + c4;
        sAoff[jj] = (uint32_t)((row * LDT + c4) * 4);
        sBoff[jj] = (uint32_t)((2 * TILEF + row * LDT + c4) * 4);
    }

#pragma unroll
    for (int jj = 0; jj < 4; jj++) {
        CP_ASYNC16(sa + sAoff[jj], Ag[jj]);
        CP_ASYNC16(sa + sBoff[jj], Wg[jj]);
    }
    CP_COMMIT();

    float acc[4][4][4];
#pragma unroll
    for (int mt = 0; mt < 4; mt++)
#pragma unroll
        for (int nt = 0; nt < 4; nt++)
#pragma unroll
            for (int r = 0; r < 4; r++) acc[mt][nt][r] = 0.f;

    for (int it = 0; it < GNIT; it++) {
        CP_WAIT(0);
        __syncthreads();

        if (it + 1 < GNIT) {
            const uint32_t dst = (uint32_t)(((it + 1) & 1) * TILEF * 4);
            const int koff = (it + 1) * GBK;
#pragma unroll
            for (int jj = 0; jj < 4; jj++) {
                CP_ASYNC16(sa + sAoff[jj] + dst, Ag[jj] + koff);
                CP_ASYNC16(sa + sBoff[jj] + dst, Wg[jj] + koff);
            }
            CP_COMMIT();
        }

        const float* Ab = As + (it & 1) * TILEF;
        const float* Bb = Bs + (it & 1) * TILEF;

#pragma unroll
        for (int ks = 0; ks < 4; ks++) {
            const int kb = ks * 8;
            uint32_t bf[4][2];
#pragma unroll
            for (int nt = 0; nt < 4; nt++) {
                const float* bp = Bb + (wn + nt * 8 + g) * LDT + kb + t;
                bf[nt][0] = f2tf32(bp[0]);
                bf[nt][1] = f2tf32(bp[4]);
            }
#pragma unroll
            for (int mt = 0; mt < 4; mt++) {
                const float* ap = Ab + (wm + mt * 16 + g) * LDT + kb + t;
                uint32_t a0 = f2tf32(ap[0]);
                uint32_t a1 = f2tf32(ap[8 * LDT]);
                uint32_t a2 = f2tf32(ap[4]);
                uint32_t a3 = f2tf32(ap[8 * LDT + 4]);
#pragma unroll
                for (int nt = 0; nt < 4; nt++)
                    mma_tf32(acc[mt][nt][0], acc[mt][nt][1],
                             acc[mt][nt][2], acc[mt][nt][3],
                             a0, a1, a2, a3, bf[nt][0], bf[nt][1]);
            }
        }
        __syncthreads();
    }

#pragma unroll
    for (int mt = 0; mt < 4; mt++) {
        const int row = bm + wm + mt * 16 + g;
#pragma unroll
        for (int nt = 0; nt < 4; nt++) {
            const int col = bn + wn + nt * 8 + 2 * t;
            const float b0 = j.bias[col], b1 = j.bias[col + 1];
            float* c0p = j.C + (size_t)row * DMODEL + col;
            float* c1p = j.C + (size_t)(row + 8) * DMODEL + col;
            *(float2*)c0p = make_float2(acc[mt][nt][0] + b0, acc[mt][nt][1] + b1);
            *(float2*)c1p = make_float2(acc[mt][nt][2] + b0, acc[mt][nt][3] + b1);
        }
    }
}

// ===========================================================================
// Tensor-core flash attention v2:
//  - 2-pass compensated tf32 (q exact / k trunc; P exact / V trunc)
//  - cp.async double-buffered K/V tiles
//  - warp-local softmax (scatter->softmax->PV need only __syncwarp)
//  - magic-number FMA exp2
// grid (SEQ/64, H, B), 128 threads = 4 warps; warp w owns query rows 16w..16w+15.
// ===========================================================================
#define ALD 68   // ld for K bufs / Pb / Ps
#define VLD 72   // ld for V bufs
#define KBUF 4352            // 64*68 floats
#define VBUF 4608            // 64*72 floats
// floats: K0 K1 | V0 V1 | Pb | Ps | stats
#define OFF_V  (2 * KBUF)                 // 8704
#define OFF_PB (2 * KBUF + 2 * VBUF)      // 17920
#define OFF_PS (OFF_PB + KBUF)            // 22272
#define OFF_ST (OFF_PS + KBUF)            // 26624
#define ATT_SMEMF (OFF_ST + 192)
#define ATT_SMEMB (ATT_SMEMF * 4)

__global__ __launch_bounds__(128) void attn_mma()
{
    extern __shared__ float sm[];
    float* Pb   = sm + OFF_PB;
    float* Ps   = sm + OFF_PS;
    float* mrow = sm + OFF_ST;
    float* lrow = sm + OFF_ST + 64;
    float* crow = sm + OFF_ST + 128;
    const uint32_t s0 = smem_u32(sm);

    const int tid = threadIdx.x;
    const int wid = tid >> 5;
    const int lid = tid & 31;
    const int g = lid >> 2;
    const int t = lid & 3;
    const int m0 = wid * 16;
    const int h = blockIdx.y;
    const int b = blockIdx.z;
    const int qbase = b * SEQ + blockIdx.x * 64;

    const float* qg = g_qp + (size_t)qbase * DMODEL + h * DK;
    const float* kg = g_kp + (size_t)b * SEQ * DMODEL + h * DK;
    const float* vg = g_vp + (size_t)b * SEQ * DMODEL + h * DK;

    // per-thread tile-load geometry: 8 float4 each for K and V
    const int rr = tid >> 4;            // base row (0..7)
    const int cc = (tid & 15) << 2;     // col (0..60)

    // ---- prefetch tile 0 into buffer 0 ----
#pragma unroll
    for (int i = 0; i < 8; i++) {
        int r = rr + i * 8;
        CP_ASYNC16(s0 + (uint32_t)((r * ALD + cc) * 4),
                   kg + (size_t)r * DMODEL + cc);
        CP_ASYNC16(s0 + (uint32_t)((OFF_V + r * VLD + cc) * 4),
                   vg + (size_t)r * DMODEL + cc);
    }
    CP_COMMIT();

    // ---- stage Q tile into Pb, init stats ----
#pragma unroll
    for (int i = 0; i < 8; i++) {
        int r = rr + i * 8;
        *(float4*)&Pb[r * ALD + cc] = *(const float4*)(qg + (size_t)r * DMODEL + cc);
    }
    if (tid < 64) { mrow[tid] = -1e30f; lrow[tid] = 0.f; }
    __syncthreads();

    // ---- preload scaled+split Q fragments ----
    uint32_t qb[8][4], qs[8][4];
#pragma unroll
    for (int ks = 0; ks < 8; ks++) {
        int kb = ks * 8;
        float f0 = Pb[(m0 + g) * ALD + kb + t] * 0.125f;
        float f1 = Pb[(m0 + g + 8) * ALD + kb + t] * 0.125f;
        float f2 = Pb[(m0 + g) * ALD + kb + t + 4] * 0.125f;
        float f3 = Pb[(m0 + g + 8) * ALD + kb + t + 4] * 0.125f;
        qb[ks][0] = f2tf32(f0); qs[ks][0] = f2tf32(f0 - __uint_as_float(qb[ks][0]));
        qb[ks][1] = f2tf32(f1); qs[ks][1] = f2tf32(f1 - __uint_as_float(qb[ks][1]));
        qb[ks][2] = f2tf32(f2); qs[ks][2] = f2tf32(f2 - __uint_as_float(qb[ks][2]));
        qb[ks][3] = f2tf32(f3); qs[ks][3] = f2tf32(f3 - __uint_as_float(qb[ks][3]));
    }

    float Oa[8][4];
#pragma unroll
    for (int nt = 0; nt < 8; nt++)
#pragma unroll
        for (int r = 0; r < 4; r++) Oa[nt][r] = 0.f;

    const int NT = SEQ / 64;
    for (int tt = 0; tt < NT; tt++) {
        // prefetch next tile into other buffer; wait for current
        if (tt + 1 < NT) {
            const int buf = (tt + 1) & 1;
            const size_t gof = (size_t)(tt + 1) * 64 * DMODEL;
#pragma unroll
            for (int i = 0; i < 8; i++) {
                int r = rr + i * 8;
                CP_ASYNC16(s0 + (uint32_t)((buf * KBUF + r * ALD + cc) * 4),
                           kg + gof + (size_t)r * DMODEL + cc);
                CP_ASYNC16(s0 + (uint32_t)((OFF_V + buf * VBUF + r * VLD + cc) * 4),
                           vg + gof + (size_t)r * DMODEL + cc);
            }
            CP_COMMIT();
            CP_WAIT(1);
        } else {
            CP_WAIT(0);
        }
        __syncthreads();

        const float* Kc = sm + (tt & 1) * KBUF;
        const float* Vc = sm + OFF_V + (tt & 1) * VBUF;

        // ---- QK^T: S = qb*kb + qs*kb (q exact, k truncated) ----
        float Sa[8][4];
#pragma unroll
        for (int nt = 0; nt < 8; nt++)
#pragma unroll
            for (int r = 0; r < 4; r++) Sa[nt][r] = 0.f;

#pragma unroll
        for (int ks = 0; ks < 8; ks++) {
            int kb = ks * 8;
#pragma unroll
            for (int nt = 0; nt < 8; nt++) {
                const float* bp = Kc + (nt * 8 + g) * ALD + kb + t;
                uint32_t bb0 = f2tf32(bp[0]);
                uint32_t bb1 = f2tf32(bp[4]);
                mma_tf32(Sa[nt][0], Sa[nt][1], Sa[nt][2], Sa[nt][3],
                         qb[ks][0], qb[ks][1], qb[ks][2], qb[ks][3], bb0, bb1);
                mma_tf32(Sa[nt][0], Sa[nt][1], Sa[nt][2], Sa[nt][3],
                         qs[ks][0], qs[ks][1], qs[ks][2], qs[ks][3], bb0, bb1);
            }
        }
        // scatter S (warp-local rows)
#pragma unroll
        for (int nt = 0; nt < 8; nt++) {
            int ccol = nt * 8 + 2 * t;
            *(float2*)&Pb[(m0 + g) * ALD + ccol]     = make_float2(Sa[nt][0], Sa[nt][1]);
            *(float2*)&Pb[(m0 + g + 8) * ALD + ccol] = make_float2(Sa[nt][2], Sa[nt][3]);
        }
        __syncwarp();

        // ---- online softmax (warp-local rows, 2 threads/row) ----
        {
            int row = tid >> 1, half = tid & 1;
            float* Sr = Pb + row * ALD + half * 32;
            float* Pr = Ps + row * ALD + half * 32;
            float4 s4[8];
            float mx = -1e30f;
#pragma unroll
            for (int i = 0; i < 8; i++) {
                s4[i] = ((float4*)Sr)[i];
                mx = fmaxf(mx, fmaxf(fmaxf(s4[i].x, s4[i].y), fmaxf(s4[i].z, s4[i].w)));
            }
            mx = fmaxf(mx, __shfl_xor_sync(0xffffffffu, mx, 1));
            float mold = mrow[row];
            float mnew = fmaxf(mold, mx);
            float ls = 0.f;
#pragma unroll
            for (int i = 0; i < 8; i++) {
                float px = exp2m((s4[i].x - mnew) * LOG2E);
                float py = exp2m((s4[i].y - mnew) * LOG2E);
                float pz = exp2m((s4[i].z - mnew) * LOG2E);
                float pw = exp2m((s4[i].w - mnew) * LOG2E);
                ls += (px + py) + (pz + pw);
                uint32_t bx = f2tf32(px), by = f2tf32(py);
                uint32_t bz = f2tf32(pz), bw = f2tf32(pw);
                ((float4*)Sr)[i] = make_float4(__uint_as_float(bx), __uint_as_float(by),
                                               __uint_as_float(bz), __uint_as_float(bw));
                ((float4*)Pr)[i] = make_float4(
                    __uint_as_float(f2tf32(px - __uint_as_float(bx))),
                    __uint_as_float(f2tf32(py - __uint_as_float(by))),
                    __uint_as_float(f2tf32(pz - __uint_as_float(bz))),
                    __uint_as_float(f2tf32(pw - __uint_as_float(bw))));
            }
            ls += __shfl_xor_sync(0xffffffffu, ls, 1);
            if (half == 0) {
                float cf = exp2m((mold - mnew) * LOG2E);
                mrow[row] = mnew;
                lrow[row] = lrow[row] * cf + ls;
                crow[row] = cf;
            }
        }
        __syncwarp();

        // ---- rescale O, then O += pb*vb + ps*vb (P exact, V truncated) ----
        {
            float c0 = crow[m0 + g], c1 = crow[m0 + g + 8];
#pragma unroll
            for (int nt = 0; nt < 8; nt++) {
                Oa[nt][0] *= c0; Oa[nt][1] *= c0;
                Oa[nt][2] *= c1; Oa[nt][3] *= c1;
            }
        }
#pragma unroll
        for (int ks = 0; ks < 8; ks++) {
            int kb = ks * 8;
            uint32_t pb0 = __float_as_uint(Pb[(m0 + g) * ALD + kb + t]);
            uint32_t pb1 = __float_as_uint(Pb[(m0 + g + 8) * ALD + kb + t]);
            uint32_t pb2 = __float_as_uint(Pb[(m0 + g) * ALD + kb + t + 4]);
            uint32_t pb3 = __float_as_uint(Pb[(m0 + g + 8) * ALD + kb + t + 4]);
            uint32_t ps0 = __float_as_uint(Ps[(m0 + g) * ALD + kb + t]);
            uint32_t ps1 = __float_as_uint(Ps[(m0 + g + 8) * ALD + kb + t]);
            uint32_t ps2 = __float_as_uint(Ps[(m0 + g) * ALD + kb + t + 4]);
            uint32_t ps3 = __float_as_uint(Ps[(m0 + g + 8) * ALD + kb + t + 4]);
#pragma unroll
            for (int nt = 0; nt < 8; nt++) {
                uint32_t vb0 = f2tf32(Vc[(kb + t) * VLD + nt * 8 + g]);
                uint32_t vb1 = f2tf32(Vc[(kb + t + 4) * VLD + nt * 8 + g]);
                mma_tf32(Oa[nt][0], Oa[nt][1], Oa[nt][2], Oa[nt][3],
                         pb0, pb1, pb2, pb3, vb0, vb1);
                mma_tf32(Oa[nt][0], Oa[nt][1], Oa[nt][2], Oa[nt][3],
                         ps0, ps1, ps2, ps3, vb0, vb1);
            }
        }
        __syncthreads();   // all reads of K/V/Pb/Ps done before next prefetch/scatter
    }

    // ---- epilogue ----
    float inv0 = 1.0f / lrow[m0 + g];
    float inv1 = 1.0f / lrow[m0 + g + 8];
    float* o0 = g_ao + (size_t)(qbase + m0 + g) * DMODEL + h * DK;
    float* o1 = g_ao + (size_t)(qbase + m0 + g + 8) * DMODEL + h * DK;
#pragma unroll
    for (int nt = 0; nt < 8; nt++) {
        int ccol = nt * 8 + 2 * t;
        *(float2*)(o0 + ccol) = make_float2(Oa[nt][0] * inv0, Oa[nt][1] * inv0);
        *(float2*)(o1 + ccol) = make_float2(Oa[nt][2] * inv1, Oa[nt][3] * inv1);
    }
}

// ===========================================================================
extern "C" void kernel_launch(void* const* d_in, const int* in_sizes, int n_in,
                              void* d_out, int out_size)
{
    const float* v  = (const float*)d_in[0];
    const float* k  = (const float*)d_in[1];
    const float* q  = (const float*)d_in[2];
    const float* Wv = (const float*)d_in[3];
    const float* bv = (const float*)d_in[4];
    const float* Wk = (const float*)d_in[5];
    const float* bk = (const float*)d_in[6];
    const float* Wq = (const float*)d_in[7];
    const float* bq = (const float*)d_in[8];
    const float* Wo = (const float*)d_in[9];
    const float* bo = (const float*)d_in[10];
    float* out = (float*)d_out;

    float *qp, *kp, *vp, *ao;
    cudaGetSymbolAddress((void**)&qp, g_qp);
    cudaGetSymbolAddress((void**)&kp, g_kp);
    cudaGetSymbolAddress((void**)&vp, g_vp);
    cudaGetSymbolAddress((void**)&ao, g_ao);

    static bool attr_set = false;
    if (!attr_set) {
        cudaFuncSetAttribute(gemm_tf32,
                             cudaFuncAttributeMaxDynamicSharedMemorySize, SMEM_REQ);
        cudaFuncSetAttribute(attn_mma,
                             cudaFuncAttributeMaxDynamicSharedMemorySize, ATT_SMEMB);
        attr_set = true;
    }

    GemmParams pin;
    pin.job[0] = { q, Wq, bq, qp };
    pin.job[1] = { k, Wk, bk, kp };
    pin.job[2] = { v, Wv, bv, vp };
    dim3 ggrid(DMODEL / GBN, MROWS / GBM, 3);   // (8, 32, 3)
    gemm_tf32<<<ggrid, 256, SMEM_REQ>>>(pin);

    dim3 attn_grid(SEQ / 64, NHEADS, BATCH);    // (32, 16, 2)
    attn_mma<<<attn_grid, 128, ATT_SMEMB>>>();

    GemmParams pout;
    pout.job[0] = { ao, Wo, bo, out };
    pout.job[1] = { ao, Wo, bo, out };
    pout.job[2] = { ao, Wo, bo, out };
    dim3 ogrid(DMODEL / GBN, MROWS / GBM, 1);   // (8, 32, 1)
    gemm_tf32<<<ogrid, 256, SMEM_REQ>>>(pout);
}